// round 16
// baseline (speedup 1.0000x reference)
#include <cuda_runtime.h>
#include <cuda_fp16.h>
#include <cstdint>

#define B_  64
#define T_  512
#define H_  512
#define NCTA 128

// ---------------- persist smem layout (single-pass W) --------------------------
#define HB 520
#define HSLICE (B_ * HB * 2)                // 66560 bytes
#define SM_H  0
#define SM_WH HSLICE                        // 66560 (32 rows x 520 x 2 = 33280)
#define SM_MB (SM_WH + 32 * HB * 2)         // 99840 (mbarrier)
#define SM_HBUF (SM_MB + 64)                // h bounce buffer: [64][8] fp16
#define PERSIST_SMEM (SM_HBUF + 1024)       // 100928

// ---------------- pre_tc smem layout (single-pass W) ---------------------------
#define PT_XS 0                              // [128][72] fp16 = 18432
#define PT_WH 18432                          // [64][72] fp16 = 9216
#define PT_BUF 27648
#define PT_BIAS (2 * PT_BUF)                 // 55296 (+256)
#define PT_SMEM (PT_BIAS + 256)              // 55552

// ---------------- scratch (device globals; no runtime allocation) ----------
__device__ float g_pre[2][T_][B_][2048];            // x@Wih^T + bias  (512 MB)
__device__ __align__(16) __half g_hf[2][2][B_][HB]; // h fp16, ping-pong (padded)
__device__ unsigned g_cnt[2 * 32];                  // per-dir arrival counter
__device__ unsigned g_preflag[2][256];              // per-(dir,tpair) tile counter
__device__ __align__(16) __half g_xh[32768 * 512];  // x fp16 [m=t*64+b][k] (32MB)
__device__ __align__(16) __half g_Wh[2 * 2048 * 512];  // Wih fp16

// ---------------- helpers -----------------------------------------------------
__device__ __forceinline__ unsigned ld_acq(const unsigned* p) {
    unsigned v;
    asm volatile("ld.global.acquire.gpu.u32 %0, [%1];" : "=r"(v) : "l"(p));
    return v;
}
__device__ __forceinline__ unsigned atom_add_rel(unsigned* p, unsigned v) {
    unsigned old;
    asm volatile("atom.add.release.gpu.u32 %0, [%1], %2;"
                 : "=r"(old) : "l"(p), "r"(v) : "memory");
    return old;
}
__device__ __forceinline__ float tanh_fast(float x) {
    float y;
    asm("tanh.approx.f32 %0, %1;" : "=f"(y) : "f"(x));
    return y;
}
__device__ __forceinline__ float sigmoid_fast(float x) {
    return fmaf(0.5f, tanh_fast(0.5f * x), 0.5f);
}
__device__ __forceinline__ void ldsm4(uint32_t r[4], uint32_t addr) {
    asm volatile("ldmatrix.sync.aligned.m8n8.x4.shared.b16 {%0,%1,%2,%3}, [%4];"
                 : "=r"(r[0]), "=r"(r[1]), "=r"(r[2]), "=r"(r[3]) : "r"(addr));
}
__device__ __forceinline__ void mma16816h(float d[4], const uint32_t a[4],
                                          uint32_t b0, uint32_t b1) {
    asm volatile(
        "mma.sync.aligned.m16n8k16.row.col.f32.f16.f16.f32 "
        "{%0,%1,%2,%3}, {%4,%5,%6,%7}, {%8,%9}, {%0,%1,%2,%3};"
        : "+f"(d[0]), "+f"(d[1]), "+f"(d[2]), "+f"(d[3])
        : "r"(a[0]), "r"(a[1]), "r"(a[2]), "r"(a[3]), "r"(b0), "r"(b1));
}
__device__ __forceinline__ void mbar_init(uint32_t a, uint32_t cnt) {
    asm volatile("mbarrier.init.shared.b64 [%0], %1;" :: "r"(a), "r"(cnt) : "memory");
}
__device__ __forceinline__ void mbar_expect_tx(uint32_t a, uint32_t tx) {
    asm volatile("mbarrier.arrive.expect_tx.shared.b64 _, [%0], %1;"
                 :: "r"(a), "r"(tx) : "memory");
}
__device__ __forceinline__ void mbar_wait(uint32_t a, uint32_t ph) {
    asm volatile(
        "{\n\t.reg .pred P;\n\t"
        "W_%=:\n\t"
        "mbarrier.try_wait.parity.acquire.cta.shared::cta.b64 P, [%0], %1, 0x989680;\n\t"
        "@!P bra W_%=;\n\t}"
        :: "r"(a), "r"(ph) : "memory");
}
__device__ __forceinline__ void bulk_cp(uint32_t dst, const void* src, uint32_t bytes,
                                        uint32_t mbar) {
    asm volatile(
        "cp.async.bulk.shared::cluster.global.mbarrier::complete_tx::bytes "
        "[%0], [%1], %2, [%3];"
        :: "r"(dst), "l"(src), "r"(bytes), "r"(mbar) : "memory");
}
__device__ __forceinline__ void cp_async16(unsigned saddr, const void* gptr) {
    asm volatile("cp.async.cg.shared.global [%0], [%1], 16;" :: "r"(saddr), "l"(gptr));
}
__device__ __forceinline__ void cp_commit() { asm volatile("cp.async.commit_group;"); }
__device__ __forceinline__ void cp_wait0()  { asm volatile("cp.async.wait_group 0;" ::: "memory"); }
__device__ __forceinline__ void cp_wait1()  { asm volatile("cp.async.wait_group 1;" ::: "memory"); }

// ---------------- dummy (profiler slot alignment) -----------------------------
__global__ void dummy_k() {}

// ---------------- init: h0 fp16 scatter + counters reset -----------------------
__global__ void init_k(const float* __restrict__ enc_h) {
    int i = blockIdx.x * blockDim.x + threadIdx.x;   // 0 .. 65535
    int n = i & 511;
    int b = (i >> 9) & 63;
    int d = i >> 15;
    g_hf[0][d][b][n] = __float2half_rn(enc_h[b * 1024 + d * 512 + n]);
    if (i < 64)  g_cnt[i] = 0;
    if (i < 512) ((unsigned*)g_preflag)[i] = 0;
}

// ---------------- convert x -> fp16 [m=t*64+b][k] ------------------------------
__global__ __launch_bounds__(256) void cvtX_k(const float* __restrict__ x) {
    int idx = blockIdx.x * 256 + threadIdx.x;
    int e   = idx * 4;
    int b   = e >> 18;
    int rem = e & 262143;
    int t   = rem >> 9;
    int k   = rem & 511;
    float4 v = *(const float4*)(x + e);
    __half2* dp = (__half2*)&g_xh[((size_t)(t * 64 + b) << 9) + k];
    dp[0] = __floats2half2_rn(v.x, v.y);
    dp[1] = __floats2half2_rn(v.z, v.w);
}

// ---------------- convert Wih -> fp16 ------------------------------------------
__global__ __launch_bounds__(256) void cvtW_k(const float* __restrict__ Wf,
                                              const float* __restrict__ Wb) {
    int idx = blockIdx.x * 256 + threadIdx.x;
    int e   = idx * 4;
    int d   = e >> 20;
    int rem = e & 1048575;
    const float* src = d ? Wb : Wf;
    float4 v = *(const float4*)(src + rem);
    __half2* dh = (__half2*)&g_Wh[(size_t)d * 1048576 + rem];
    dh[0] = __floats2half2_rn(v.x, v.y);
    dh[1] = __floats2half2_rn(v.z, v.w);
}

// ---------------- pre_tc: stage one 64-k chunk ---------------------------------
__device__ __forceinline__ void pre_stage(uint32_t sb, int buf, int k0, int t0,
                                          int j0, int d, int tid,
                                          const __half* Whg) {
    uint32_t base = sb + buf * PT_BUF;
#pragma unroll
    for (int i = 0; i < 4; i++) {
        int q  = tid + i * 256;
        int r  = q >> 3;
        int ko = (q & 7) * 8;
        int t  = t0 + (r >> 6);
        int tx = d ? (511 - t) : t;
        size_t grow = (size_t)(tx * 64 + (r & 63));
        cp_async16(base + PT_XS + (uint32_t)(r * 72 + ko) * 2,
                   g_xh + (grow << 9) + k0 + ko);
    }
#pragma unroll
    for (int i = 0; i < 2; i++) {
        int q  = tid + i * 256;
        int r  = q >> 3;
        int ko = (q & 7) * 8;
        size_t src = ((size_t)(j0 + r) << 9) + k0 + ko;
        cp_async16(base + PT_WH + (uint32_t)(r * 72 + ko) * 2, Whg + src);
    }
}

// ---------------- precompute GEMM on tensor cores (fp16 1-pass) ---------------
// grid (32 j-tiles, 512 y = tpair*2+d): t-ordered production, dirs interleaved.
__global__ __launch_bounds__(256, 2) void pre_tc(const float* __restrict__ bf,
                                                 const float* __restrict__ bb_) {
    extern __shared__ char sm[];
    const uint32_t sb = (uint32_t)__cvta_generic_to_shared(sm);
    const int tid = threadIdx.x;
    const int w   = tid >> 5;
    const int l   = tid & 31;
    const int y   = blockIdx.y;
    const int d   = y & 1;
    const int tp  = y >> 1;                    // tpair = m-tile index
    const int j0  = blockIdx.x * 64;
    const int t0  = tp * 2;
    const __half* Whg = g_Wh + (size_t)d * 1048576;
    const float* bias = d ? bb_ : bf;

    float* bias_s = (float*)(sm + PT_BIAS);
    if (tid < 64) bias_s[tid] = bias[j0 + tid];

    const int wr = w >> 2;
    const int wc = w & 3;
    const uint32_t a_row = (uint32_t)(wr * 64 + (l & 15));
    const uint32_t a_col = (uint32_t)((l >> 4) * 8);
    const uint32_t b_row = (uint32_t)(wc * 16 + ((l >> 4) & 1) * 8 + (l & 7));
    const uint32_t b_col = (uint32_t)(((l >> 3) & 1) * 8);

    float acc[4][2][4];
#pragma unroll
    for (int i = 0; i < 4; i++)
#pragma unroll
        for (int j = 0; j < 2; j++)
#pragma unroll
            for (int q = 0; q < 4; q++) acc[i][j][q] = 0.f;

    pre_stage(sb, 0, 0, t0, j0, d, tid, Whg);
    cp_commit();

    for (int c = 0; c < 8; c++) {
        if (c + 1 < 8) {
            pre_stage(sb, (c + 1) & 1, (c + 1) * 64, t0, j0, d, tid, Whg);
            cp_commit();
            cp_wait1();
        } else {
            cp_wait0();
        }
        __syncthreads();
        uint32_t base = sb + (c & 1) * PT_BUF;
#pragma unroll
        for (int kk = 0; kk < 64; kk += 16) {
            uint32_t bh[4], a[4][4];
            ldsm4(bh, base + PT_WH + (b_row * 72 + b_col + kk) * 2);
#pragma unroll
            for (int i = 0; i < 4; i++)
                ldsm4(a[i], base + PT_XS + ((a_row + i * 16) * 72 + a_col + kk) * 2);
#pragma unroll
            for (int i = 0; i < 4; i++) {
                mma16816h(acc[i][0], a[i], bh[0], bh[1]);
                mma16816h(acc[i][1], a[i], bh[2], bh[3]);
            }
        }
        __syncthreads();
    }

#pragma unroll
    for (int i = 0; i < 4; i++)
#pragma unroll
        for (int jt = 0; jt < 2; jt++) {
            int jloc = wc * 16 + jt * 8 + 2 * (l & 3);
            float bx = bias_s[jloc];
            float by = bias_s[jloc + 1];
#pragma unroll
            for (int rr = 0; rr < 2; rr++) {
                int m = tp * 128 + wr * 64 + i * 16 + (l >> 2) + rr * 8;
                int t = m >> 6;
                int b = m & 63;
                float2 o = make_float2(acc[i][jt][rr * 2 + 0] + bx,
                                       acc[i][jt][rr * 2 + 1] + by);
                *(float2*)&g_pre[d][t][b][j0 + jloc] = o;
            }
        }

    __syncthreads();
    if (tid == 0) atom_add_rel(&g_preflag[d][tp], 1u);
}

// ---------------- persistent HMMA recurrence (single-pass W) -------------------
__global__ __launch_bounds__(256, 1) void persist_k(const float* __restrict__ Whf,
                                                    const float* __restrict__ Whb,
                                                    const float* __restrict__ enc_c,
                                                    float* __restrict__ out) {
    extern __shared__ char sm[];
    const uint32_t sb = (uint32_t)__cvta_generic_to_shared(sm);
    __half* Wh_s = (__half*)(sm + SM_WH);
    __half (*hb)[8] = (__half(*)[8])(sm + SM_HBUF);           // [64][8]
    const uint32_t mbar = sb + SM_MB;

    const int d   = blockIdx.x >> 6;
    const int n0  = (blockIdx.x & 63) * 8;
    const int tid = threadIdx.x;
    const int w   = tid >> 5;
    const int l   = tid & 31;
    const float* __restrict__ W = d ? Whb : Whf;

    unsigned* cnt = &g_cnt[d * 32];

    // ---- convert resident W tile to fp16 in smem (rows c = nl*4+gate) ----
    for (int i = tid; i < 32 * 512; i += 256) {
        int r = i >> 9;
        int k = i & 511;
        int j = (r & 3) * 512 + n0 + (r >> 2);
        Wh_s[r * HB + k] = __float2half_rn(W[(size_t)j * 512 + k]);
    }

    // ---- per-lane geometry ----
    const int m0 = (w & 3) * 16;
    const int jb = (w >> 2) * 16;
    const uint32_t aoff = (uint32_t)(((m0 + (l & 15)) * HB + ((l >> 4) * 8)) * 2);
    const uint32_t boff = (uint32_t)(((jb + ((l >> 4) & 1) * 8 + (l & 7)) * HB
                                      + (((l >> 3) & 1) * 8)) * 2);
    const uint32_t aHb = sb + SM_H + aoff;
    const uint32_t bHb = sb + SM_WH + boff;

    const int b_out = m0 + (l >> 2) + ((l & 1) ? 8 : 0);
    const int nlb   = (jb >> 2) + ((l & 2) >> 1);

    float c_reg[2];
#pragma unroll
    for (int t2 = 0; t2 < 2; t2++)
        c_reg[t2] = enc_c[b_out * 1024 + d * 512 + n0 + nlb + 2 * t2];

    if (tid == 0) mbar_init(mbar, 1);
    __syncthreads();

    if (tid == 0) {
        mbar_expect_tx(mbar, HSLICE);
        bulk_cp(sb + SM_H, &g_hf[0][d][0][0], HSLICE, mbar);
    }

    // ---- wait for pre tpair 0, then prime pipeline ----
    while (ld_acq(&g_preflag[d][0]) < 32u) {}
    float pre_cur[2][4], pre_next[2][4];
#pragma unroll
    for (int t2 = 0; t2 < 2; t2++)
#pragma unroll
        for (int g = 0; g < 4; g++)
            pre_cur[t2][g] = __ldcs(&g_pre[d][0][b_out][g * 512 + n0 + nlb + 2 * t2]);

    int mph = 0;
    for (int t = 0; t < 512; t++) {
        const int ph = t & 1;

        // ---- prefetch NEXT step's pre-activations (flag-gated per tpair) ----
        if (t + 1 < 512) {
            if (((t + 1) & 1) == 0) {
                const unsigned* fp = &g_preflag[d][(t + 1) >> 1];
                while (ld_acq(fp) < 32u) {}
            }
#pragma unroll
            for (int t2 = 0; t2 < 2; t2++)
#pragma unroll
                for (int g = 0; g < 4; g++)
                    pre_next[t2][g] =
                        __ldcs(&g_pre[d][t + 1][b_out][g * 512 + n0 + nlb + 2 * t2]);
        }

        mbar_wait(mbar, mph);
        mph ^= 1;

        // ---- HMMA k-loop: 32 k16 steps x (2 ldsm + 2 mma) ----
        float acc0[4] = {0, 0, 0, 0}, acc1[4] = {0, 0, 0, 0};
#pragma unroll 4
        for (int kk = 0; kk < 512; kk += 16) {
            uint32_t ah[4], bh[4];
            ldsm4(ah, aHb + kk * 2);
            ldsm4(bh, bHb + kk * 2);
            mma16816h(acc0, ah, bh[0], bh[1]);
            mma16816h(acc1, ah, bh[2], bh[3]);
        }

        const int odd = l & 1;
        float h_res[2];
        float* accs[2] = {acc0, acc1};
#pragma unroll
        for (int t2 = 0; t2 < 2; t2++) {
            float* a = accs[t2];
            float r0 = __shfl_xor_sync(0xFFFFFFFFu, odd ? a[0] : a[2], 1);
            float r1 = __shfl_xor_sync(0xFFFFFFFFu, odd ? a[1] : a[3], 1);
            float g0 = odd ? r0 : a[0];
            float g1 = odd ? r1 : a[1];
            float g2 = odd ? a[2] : r0;
            float g3 = odd ? a[3] : r1;

            float gi = pre_cur[t2][0] + g0;
            float gf = pre_cur[t2][1] + g1;
            float gg = pre_cur[t2][2] + g2;
            float go = pre_cur[t2][3] + g3;
            float si = sigmoid_fast(gi);
            float sf = sigmoid_fast(gf);
            float tg = tanh_fast(gg);
            float so = sigmoid_fast(go);
            float c  = sf * c_reg[t2] + si * tg;
            float h  = so * tanh_fast(c);
            c_reg[t2] = c;
            h_res[t2] = h;

            hb[b_out][nlb + 2 * t2] = __float2half_rn(h);
        }
        __syncthreads();

        if (tid < 64)
            *(uint4*)&g_hf[ph ^ 1][d][tid][n0] = *(const uint4*)&hb[tid][0];

        if (t < 511) {
            __syncthreads();
            if (tid == 0) {
                atom_add_rel(cnt, 1u);
                unsigned target = 64u * (unsigned)(t + 1);
                while (ld_acq(cnt) < target) {}
                mbar_expect_tx(mbar, HSLICE);
                bulk_cp(sb + SM_H, &g_hf[(ph ^ 1)][d][0][0], HSLICE, mbar);
            }
            __syncthreads();
        }

        const int tout = d ? (511 - t) : t;
#pragma unroll
        for (int t2 = 0; t2 < 2; t2++) {
            const int n = n0 + nlb + 2 * t2;
            __stcs(&out[((size_t)b_out * 512 + tout) * 1024 + d * 512 + n], h_res[t2]);
            if (t == 511) {
                __stcs(&out[33554432 + b_out * 1024 + d * 512 + n], h_res[t2]);
                __stcs(&out[33554432 + 65536 + b_out * 1024 + d * 512 + n], c_reg[t2]);
            }
        }

#pragma unroll
        for (int t2 = 0; t2 < 2; t2++)
#pragma unroll
            for (int g = 0; g < 4; g++) pre_cur[t2][g] = pre_next[t2][g];
    }
}

// ---------------- launch -----------------------------------------------------
extern "C" void kernel_launch(void* const* d_in, const int* in_sizes, int n_in,
                              void* d_out, int out_size) {
    const float* x     = (const float*)d_in[0];
    const float* enc_h = (const float*)d_in[1];
    const float* enc_c = (const float*)d_in[2];
    const float* Wih_f = (const float*)d_in[3];
    const float* Whh_f = (const float*)d_in[4];
    const float* b_f   = (const float*)d_in[5];
    const float* Wih_b = (const float*)d_in[6];
    const float* Whh_b = (const float*)d_in[7];
    const float* b_b   = (const float*)d_in[8];
    float* out = (float*)d_out;

    static cudaStream_t s2 = nullptr;
    static cudaEvent_t  e1 = nullptr, e2 = nullptr;
    if (!s2) {
        cudaStreamCreateWithFlags(&s2, cudaStreamNonBlocking);
        cudaEventCreateWithFlags(&e1, cudaEventDisableTiming);
        cudaEventCreateWithFlags(&e2, cudaEventDisableTiming);
        cudaFuncSetAttribute(persist_k, cudaFuncAttributeMaxDynamicSharedMemorySize,
                             PERSIST_SMEM);
        cudaFuncSetAttribute(pre_tc, cudaFuncAttributeMaxDynamicSharedMemorySize,
                             PT_SMEM);
    }

    dummy_k<<<1, 32>>>();
    init_k<<<256, 256>>>(enc_h);
    cvtX_k<<<16384, 256>>>(x);
    cvtW_k<<<2048, 256>>>(Wih_f, Wih_b);

    // fork: pre_tc overlaps persist_k (now smem-compatible for co-residency)
    cudaEventRecord(e1, 0);
    cudaStreamWaitEvent(s2, e1, 0);
    pre_tc<<<dim3(32, 512, 1), 256, PT_SMEM, s2>>>(b_f, b_b);
    cudaEventRecord(e2, s2);

    persist_k<<<NCTA, 256, PERSIST_SMEM>>>(Whh_f, Whh_b, enc_c, out);

    cudaStreamWaitEvent(0, e2, 0);
}

// round 17
// speedup vs baseline: 1.4443x; 1.4443x over previous
#include <cuda_runtime.h>
#include <cuda_fp16.h>
#include <cstdint>

#define B_  64
#define T_  512
#define H_  512
#define NCTA 128

// ---------------- persist smem layout (single-pass W) --------------------------
#define HB 520
#define HSLICE (B_ * HB * 2)                // 66560 bytes
#define SM_H  0
#define SM_WH HSLICE                        // 66560 (32 rows x 520 x 2 = 33280)
#define SM_MB (SM_WH + 32 * HB * 2)         // 99840 (mbarrier)
#define SM_HBUF (SM_MB + 64)                // h bounce buffer: [64][8] fp16
#define PERSIST_SMEM (SM_HBUF + 1024)       // 100928

// ---------------- pre_tc smem layout (single-pass W) ---------------------------
#define PT_XS 0                              // [128][72] fp16 = 18432
#define PT_WH 18432                          // [64][72] fp16 = 9216
#define PT_BUF 27648
#define PT_BIAS (2 * PT_BUF)                 // 55296 (+256)
#define PT_SMEM (PT_BIAS + 256)              // 55552

// ---------------- scratch (device globals; no runtime allocation) ----------
__device__ float g_pre[2][T_][B_][2048];            // x@Wih^T + bias  (512 MB)
__device__ __align__(16) __half g_hf[2][2][B_][HB]; // h fp16, ping-pong (padded)
__device__ unsigned g_cnt[2 * 32];                  // per-dir arrival counter
__device__ __align__(16) __half g_xh[32768 * 512];  // x fp16 [m=t*64+b][k] (32MB)
__device__ __align__(16) __half g_Wh[2 * 2048 * 512];  // Wih fp16

// ---------------- helpers -----------------------------------------------------
__device__ __forceinline__ unsigned ld_acq(const unsigned* p) {
    unsigned v;
    asm volatile("ld.global.acquire.gpu.u32 %0, [%1];" : "=r"(v) : "l"(p));
    return v;
}
__device__ __forceinline__ unsigned atom_add_rel(unsigned* p, unsigned v) {
    unsigned old;
    asm volatile("atom.add.release.gpu.u32 %0, [%1], %2;"
                 : "=r"(old) : "l"(p), "r"(v) : "memory");
    return old;
}
__device__ __forceinline__ float tanh_fast(float x) {
    float y;
    asm("tanh.approx.f32 %0, %1;" : "=f"(y) : "f"(x));
    return y;
}
__device__ __forceinline__ float sigmoid_fast(float x) {
    return fmaf(0.5f, tanh_fast(0.5f * x), 0.5f);
}
__device__ __forceinline__ void ldsm4(uint32_t r[4], uint32_t addr) {
    asm volatile("ldmatrix.sync.aligned.m8n8.x4.shared.b16 {%0,%1,%2,%3}, [%4];"
                 : "=r"(r[0]), "=r"(r[1]), "=r"(r[2]), "=r"(r[3]) : "r"(addr));
}
__device__ __forceinline__ void mma16816h(float d[4], const uint32_t a[4],
                                          uint32_t b0, uint32_t b1) {
    asm volatile(
        "mma.sync.aligned.m16n8k16.row.col.f32.f16.f16.f32 "
        "{%0,%1,%2,%3}, {%4,%5,%6,%7}, {%8,%9}, {%0,%1,%2,%3};"
        : "+f"(d[0]), "+f"(d[1]), "+f"(d[2]), "+f"(d[3])
        : "r"(a[0]), "r"(a[1]), "r"(a[2]), "r"(a[3]), "r"(b0), "r"(b1));
}
__device__ __forceinline__ void mbar_init(uint32_t a, uint32_t cnt) {
    asm volatile("mbarrier.init.shared.b64 [%0], %1;" :: "r"(a), "r"(cnt) : "memory");
}
__device__ __forceinline__ void mbar_expect_tx(uint32_t a, uint32_t tx) {
    asm volatile("mbarrier.arrive.expect_tx.shared.b64 _, [%0], %1;"
                 :: "r"(a), "r"(tx) : "memory");
}
__device__ __forceinline__ void mbar_wait(uint32_t a, uint32_t ph) {
    asm volatile(
        "{\n\t.reg .pred P;\n\t"
        "W_%=:\n\t"
        "mbarrier.try_wait.parity.acquire.cta.shared::cta.b64 P, [%0], %1, 0x989680;\n\t"
        "@!P bra W_%=;\n\t}"
        :: "r"(a), "r"(ph) : "memory");
}
__device__ __forceinline__ void bulk_cp(uint32_t dst, const void* src, uint32_t bytes,
                                        uint32_t mbar) {
    asm volatile(
        "cp.async.bulk.shared::cluster.global.mbarrier::complete_tx::bytes "
        "[%0], [%1], %2, [%3];"
        :: "r"(dst), "l"(src), "r"(bytes), "r"(mbar) : "memory");
}
__device__ __forceinline__ void cp_async16(unsigned saddr, const void* gptr) {
    asm volatile("cp.async.cg.shared.global [%0], [%1], 16;" :: "r"(saddr), "l"(gptr));
}
__device__ __forceinline__ void cp_commit() { asm volatile("cp.async.commit_group;"); }
__device__ __forceinline__ void cp_wait0()  { asm volatile("cp.async.wait_group 0;" ::: "memory"); }
__device__ __forceinline__ void cp_wait1()  { asm volatile("cp.async.wait_group 1;" ::: "memory"); }

// ---------------- dummy (profiler slot alignment) -----------------------------
__global__ void dummy_k() {}

// ---------------- init: h0 fp16 scatter + counters reset -----------------------
__global__ void init_k(const float* __restrict__ enc_h) {
    int i = blockIdx.x * blockDim.x + threadIdx.x;   // 0 .. 65535
    int n = i & 511;
    int b = (i >> 9) & 63;
    int d = i >> 15;
    g_hf[0][d][b][n] = __float2half_rn(enc_h[b * 1024 + d * 512 + n]);
    if (i < 64) g_cnt[i] = 0;
}

// ---------------- convert x -> fp16 [m=t*64+b][k] ------------------------------
__global__ __launch_bounds__(256) void cvtX_k(const float* __restrict__ x) {
    int idx = blockIdx.x * 256 + threadIdx.x;
    int e   = idx * 4;
    int b   = e >> 18;
    int rem = e & 262143;
    int t   = rem >> 9;
    int k   = rem & 511;
    float4 v = *(const float4*)(x + e);
    __half2* dp = (__half2*)&g_xh[((size_t)(t * 64 + b) << 9) + k];
    dp[0] = __floats2half2_rn(v.x, v.y);
    dp[1] = __floats2half2_rn(v.z, v.w);
}

// ---------------- convert Wih -> fp16 ------------------------------------------
__global__ __launch_bounds__(256) void cvtW_k(const float* __restrict__ Wf,
                                              const float* __restrict__ Wb) {
    int idx = blockIdx.x * 256 + threadIdx.x;
    int e   = idx * 4;
    int d   = e >> 20;
    int rem = e & 1048575;
    const float* src = d ? Wb : Wf;
    float4 v = *(const float4*)(src + rem);
    __half2* dh = (__half2*)&g_Wh[(size_t)d * 1048576 + rem];
    dh[0] = __floats2half2_rn(v.x, v.y);
    dh[1] = __floats2half2_rn(v.z, v.w);
}

// ---------------- pre_tc: stage one 64-k chunk ---------------------------------
__device__ __forceinline__ void pre_stage(uint32_t sb, int buf, int k0, int t0,
                                          int j0, int d, int tid,
                                          const __half* Whg) {
    uint32_t base = sb + buf * PT_BUF;
#pragma unroll
    for (int i = 0; i < 4; i++) {
        int q  = tid + i * 256;
        int r  = q >> 3;
        int ko = (q & 7) * 8;
        int t  = t0 + (r >> 6);
        int tx = d ? (511 - t) : t;
        size_t grow = (size_t)(tx * 64 + (r & 63));
        cp_async16(base + PT_XS + (uint32_t)(r * 72 + ko) * 2,
                   g_xh + (grow << 9) + k0 + ko);
    }
#pragma unroll
    for (int i = 0; i < 2; i++) {
        int q  = tid + i * 256;
        int r  = q >> 3;
        int ko = (q & 7) * 8;
        size_t src = ((size_t)(j0 + r) << 9) + k0 + ko;
        cp_async16(base + PT_WH + (uint32_t)(r * 72 + ko) * 2, Whg + src);
    }
}

// ---------------- precompute GEMM on tensor cores (fp16 1-pass) ---------------
// grid (32 j-tiles, 256 m-tiles, 2 dirs), 256 threads = 8 warps (2m x 4n).
__global__ __launch_bounds__(256, 2) void pre_tc(const float* __restrict__ bf,
                                                 const float* __restrict__ bb_) {
    extern __shared__ char sm[];
    const uint32_t sb = (uint32_t)__cvta_generic_to_shared(sm);
    const int tid = threadIdx.x;
    const int w   = tid >> 5;
    const int l   = tid & 31;
    const int d   = blockIdx.z;
    const int tp  = blockIdx.y;                // m-tile index
    const int j0  = blockIdx.x * 64;
    const int t0  = tp * 2;
    const __half* Whg = g_Wh + (size_t)d * 1048576;
    const float* bias = d ? bb_ : bf;

    float* bias_s = (float*)(sm + PT_BIAS);
    if (tid < 64) bias_s[tid] = bias[j0 + tid];

    const int wr = w >> 2;
    const int wc = w & 3;
    const uint32_t a_row = (uint32_t)(wr * 64 + (l & 15));
    const uint32_t a_col = (uint32_t)((l >> 4) * 8);
    const uint32_t b_row = (uint32_t)(wc * 16 + ((l >> 4) & 1) * 8 + (l & 7));
    const uint32_t b_col = (uint32_t)(((l >> 3) & 1) * 8);

    float acc[4][2][4];
#pragma unroll
    for (int i = 0; i < 4; i++)
#pragma unroll
        for (int j = 0; j < 2; j++)
#pragma unroll
            for (int q = 0; q < 4; q++) acc[i][j][q] = 0.f;

    pre_stage(sb, 0, 0, t0, j0, d, tid, Whg);
    cp_commit();

    for (int c = 0; c < 8; c++) {
        if (c + 1 < 8) {
            pre_stage(sb, (c + 1) & 1, (c + 1) * 64, t0, j0, d, tid, Whg);
            cp_commit();
            cp_wait1();
        } else {
            cp_wait0();
        }
        __syncthreads();
        uint32_t base = sb + (c & 1) * PT_BUF;
#pragma unroll
        for (int kk = 0; kk < 64; kk += 16) {
            uint32_t bh[4], a[4][4];
            ldsm4(bh, base + PT_WH + (b_row * 72 + b_col + kk) * 2);
#pragma unroll
            for (int i = 0; i < 4; i++)
                ldsm4(a[i], base + PT_XS + ((a_row + i * 16) * 72 + a_col + kk) * 2);
#pragma unroll
            for (int i = 0; i < 4; i++) {
                mma16816h(acc[i][0], a[i], bh[0], bh[1]);
                mma16816h(acc[i][1], a[i], bh[2], bh[3]);
            }
        }
        __syncthreads();
    }

#pragma unroll
    for (int i = 0; i < 4; i++)
#pragma unroll
        for (int jt = 0; jt < 2; jt++) {
            int jloc = wc * 16 + jt * 8 + 2 * (l & 3);
            float bx = bias_s[jloc];
            float by = bias_s[jloc + 1];
#pragma unroll
            for (int rr = 0; rr < 2; rr++) {
                int m = tp * 128 + wr * 64 + i * 16 + (l >> 2) + rr * 8;
                int t = m >> 6;
                int b = m & 63;
                float2 o = make_float2(acc[i][jt][rr * 2 + 0] + bx,
                                       acc[i][jt][rr * 2 + 1] + by);
                *(float2*)&g_pre[d][t][b][j0 + jloc] = o;
            }
        }
}

// ---------------- persistent HMMA recurrence (single-pass W) -------------------
__global__ __launch_bounds__(256, 1) void persist_k(const float* __restrict__ Whf,
                                                    const float* __restrict__ Whb,
                                                    const float* __restrict__ enc_c,
                                                    float* __restrict__ out) {
    extern __shared__ char sm[];
    const uint32_t sb = (uint32_t)__cvta_generic_to_shared(sm);
    __half* Wh_s = (__half*)(sm + SM_WH);
    __half (*hb)[8] = (__half(*)[8])(sm + SM_HBUF);           // [64][8]
    const uint32_t mbar = sb + SM_MB;

    const int d   = blockIdx.x >> 6;
    const int n0  = (blockIdx.x & 63) * 8;
    const int tid = threadIdx.x;
    const int w   = tid >> 5;
    const int l   = tid & 31;
    const float* __restrict__ W = d ? Whb : Whf;

    unsigned* cnt = &g_cnt[d * 32];

    // ---- convert resident W tile to fp16 in smem (rows c = nl*4+gate) ----
    for (int i = tid; i < 32 * 512; i += 256) {
        int r = i >> 9;
        int k = i & 511;
        int j = (r & 3) * 512 + n0 + (r >> 2);
        Wh_s[r * HB + k] = __float2half_rn(W[(size_t)j * 512 + k]);
    }

    // ---- per-lane geometry ----
    const int m0 = (w & 3) * 16;
    const int jb = (w >> 2) * 16;
    const uint32_t aoff = (uint32_t)(((m0 + (l & 15)) * HB + ((l >> 4) * 8)) * 2);
    const uint32_t boff = (uint32_t)(((jb + ((l >> 4) & 1) * 8 + (l & 7)) * HB
                                      + (((l >> 3) & 1) * 8)) * 2);
    const uint32_t aHb = sb + SM_H + aoff;
    const uint32_t bHb = sb + SM_WH + boff;

    const int b_out = m0 + (l >> 2) + ((l & 1) ? 8 : 0);
    const int nlb   = (jb >> 2) + ((l & 2) >> 1);

    float c_reg[2];
#pragma unroll
    for (int t2 = 0; t2 < 2; t2++)
        c_reg[t2] = enc_c[b_out * 1024 + d * 512 + n0 + nlb + 2 * t2];

    if (tid == 0) mbar_init(mbar, 1);
    __syncthreads();

    if (tid == 0) {
        mbar_expect_tx(mbar, HSLICE);
        bulk_cp(sb + SM_H, &g_hf[0][d][0][0], HSLICE, mbar);
    }
    float pre_cur[2][4], pre_next[2][4];
#pragma unroll
    for (int t2 = 0; t2 < 2; t2++)
#pragma unroll
        for (int g = 0; g < 4; g++)
            pre_cur[t2][g] = __ldcs(&g_pre[d][0][b_out][g * 512 + n0 + nlb + 2 * t2]);

    int mph = 0;
    for (int t = 0; t < 512; t++) {
        const int ph = t & 1;

        if (t + 1 < 512) {
#pragma unroll
            for (int t2 = 0; t2 < 2; t2++)
#pragma unroll
                for (int g = 0; g < 4; g++)
                    pre_next[t2][g] =
                        __ldcs(&g_pre[d][t + 1][b_out][g * 512 + n0 + nlb + 2 * t2]);
        }

        mbar_wait(mbar, mph);
        mph ^= 1;

        // ---- HMMA k-loop: 32 k16 steps x (2 ldsm + 2 mma) ----
        float acc0[4] = {0, 0, 0, 0}, acc1[4] = {0, 0, 0, 0};
#pragma unroll 4
        for (int kk = 0; kk < 512; kk += 16) {
            uint32_t ah[4], bh[4];
            ldsm4(ah, aHb + kk * 2);
            ldsm4(bh, bHb + kk * 2);
            mma16816h(acc0, ah, bh[0], bh[1]);
            mma16816h(acc1, ah, bh[2], bh[3]);
        }

        const int odd = l & 1;
        float h_res[2];
        float* accs[2] = {acc0, acc1};
#pragma unroll
        for (int t2 = 0; t2 < 2; t2++) {
            float* a = accs[t2];
            float r0 = __shfl_xor_sync(0xFFFFFFFFu, odd ? a[0] : a[2], 1);
            float r1 = __shfl_xor_sync(0xFFFFFFFFu, odd ? a[1] : a[3], 1);
            float g0 = odd ? r0 : a[0];
            float g1 = odd ? r1 : a[1];
            float g2 = odd ? a[2] : r0;
            float g3 = odd ? a[3] : r1;

            float gi = pre_cur[t2][0] + g0;
            float gf = pre_cur[t2][1] + g1;
            float gg = pre_cur[t2][2] + g2;
            float go = pre_cur[t2][3] + g3;
            float si = sigmoid_fast(gi);
            float sf = sigmoid_fast(gf);
            float tg = tanh_fast(gg);
            float so = sigmoid_fast(go);
            float c  = sf * c_reg[t2] + si * tg;
            float h  = so * tanh_fast(c);
            c_reg[t2] = c;
            h_res[t2] = h;

            hb[b_out][nlb + 2 * t2] = __float2half_rn(h);
        }
        __syncthreads();

        if (tid < 64)
            *(uint4*)&g_hf[ph ^ 1][d][tid][n0] = *(const uint4*)&hb[tid][0];

        if (t < 511) {
            __syncthreads();
            if (tid == 0) {
                atom_add_rel(cnt, 1u);
                unsigned target = 64u * (unsigned)(t + 1);
                while (ld_acq(cnt) < target) {}
                mbar_expect_tx(mbar, HSLICE);
                bulk_cp(sb + SM_H, &g_hf[(ph ^ 1)][d][0][0], HSLICE, mbar);
            }
            __syncthreads();
        }

        const int tout = d ? (511 - t) : t;
#pragma unroll
        for (int t2 = 0; t2 < 2; t2++) {
            const int n = n0 + nlb + 2 * t2;
            __stcs(&out[((size_t)b_out * 512 + tout) * 1024 + d * 512 + n], h_res[t2]);
            if (t == 511) {
                __stcs(&out[33554432 + b_out * 1024 + d * 512 + n], h_res[t2]);
                __stcs(&out[33554432 + 65536 + b_out * 1024 + d * 512 + n], c_reg[t2]);
            }
        }

#pragma unroll
        for (int t2 = 0; t2 < 2; t2++)
#pragma unroll
            for (int g = 0; g < 4; g++) pre_cur[t2][g] = pre_next[t2][g];
    }
}

// ---------------- launch (serial: no stream fork) ------------------------------
extern "C" void kernel_launch(void* const* d_in, const int* in_sizes, int n_in,
                              void* d_out, int out_size) {
    const float* x     = (const float*)d_in[0];
    const float* enc_h = (const float*)d_in[1];
    const float* enc_c = (const float*)d_in[2];
    const float* Wih_f = (const float*)d_in[3];
    const float* Whh_f = (const float*)d_in[4];
    const float* b_f   = (const float*)d_in[5];
    const float* Wih_b = (const float*)d_in[6];
    const float* Whh_b = (const float*)d_in[7];
    const float* b_b   = (const float*)d_in[8];
    float* out = (float*)d_out;

    static int inited = 0;
    if (!inited) {
        cudaFuncSetAttribute(persist_k, cudaFuncAttributeMaxDynamicSharedMemorySize,
                             PERSIST_SMEM);
        cudaFuncSetAttribute(pre_tc, cudaFuncAttributeMaxDynamicSharedMemorySize,
                             PT_SMEM);
        inited = 1;
    }

    dummy_k<<<1, 32>>>();
    init_k<<<256, 256>>>(enc_h);
    cvtX_k<<<16384, 256>>>(x);
    cvtW_k<<<2048, 256>>>(Wih_f, Wih_b);
    pre_tc<<<dim3(32, 256, 2), 256, PT_SMEM>>>(b_f, b_b);
    persist_k<<<NCTA, 256, PERSIST_SMEM>>>(Whh_f, Whh_b, enc_c, out);
}